// round 4
// baseline (speedup 1.0000x reference)
#include <cuda_runtime.h>

// Problem constants
#define BB   16
#define CC   256
#define HH   64
#define WW   64
#define HWSZ 4096     // H*W
#define DQ   32       // C/8
#define DV   128      // C/2
#define OC   192      // 2*DQ + DV
#define MM   1024     // pooled spatial (32*32)

// Scratch (device globals: allocation-free rule)
__device__ float g_qkv[BB * OC * HWSZ];   // 50.3 MB: full qkv, q read from rows [0,32)
__device__ float g_k[BB * DQ * MM];       // pooled K
__device__ float g_v[BB * DV * MM];       // pooled V
__device__ float g_ao[BB * DV * HWSZ];    // attention output [b][d][n]

// ---- packed fp32x2 helpers (FFMA2: 2x FFMA throughput, PTX-only) ----
__device__ __forceinline__ void fma2(unsigned long long &acc, unsigned long long a, unsigned long long b) {
    asm("fma.rn.f32x2 %0, %1, %2, %0;" : "+l"(acc) : "l"(a), "l"(b));
}
__device__ __forceinline__ unsigned long long pack2(float lo, float hi) {
    unsigned long long r;
    asm("mov.b64 %0, {%1, %2};" : "=l"(r) : "f"(lo), "f"(hi));
    return r;
}
__device__ __forceinline__ float2 unp2(unsigned long long v) {
    float2 r;
    asm("mov.b64 {%0, %1}, %2;" : "=f"(r.x), "=f"(r.y) : "l"(v));
    return r;
}

// ============================================================
// K1: qkv = w_qkv @ imgs  per batch: [192x256]@[256x4096]
// tile 64(o) x 64(hw), 256 threads, 4x4 microtile via f32x2
// ============================================================
__global__ void __launch_bounds__(256) k_qkv(const float* __restrict__ imgs,
                                             const float* __restrict__ wq) {
    __shared__ float Ws[16][68];   // [c_local][o_local], padded
    __shared__ float Xs[16][64];   // [c_local][hw_local]

    const int b   = blockIdx.z;
    const int o0  = blockIdx.y * 64;
    const int hw0 = blockIdx.x * 64;
    const int tid = threadIdx.x;
    const int tx  = tid & 15;      // hw
    const int ty  = tid >> 4;      // o

    const float* X = imgs + (size_t)b * CC * HWSZ;

    unsigned long long acc[4][2];
#pragma unroll
    for (int i = 0; i < 4; i++) { acc[i][0] = 0ull; acc[i][1] = 0ull; }

    for (int kk = 0; kk < CC; kk += 16) {
#pragma unroll
        for (int e = tid; e < 1024; e += 256) {        // W chunk, transposed
            int ol = e >> 4, cl = e & 15;
            Ws[cl][ol] = wq[(size_t)(o0 + ol) * CC + kk + cl];
        }
#pragma unroll
        for (int e = tid; e < 1024; e += 256) {        // X chunk
            int cl = e >> 6, hl = e & 63;
            Xs[cl][hl] = X[(size_t)(kk + cl) * HWSZ + hw0 + hl];
        }
        __syncthreads();
#pragma unroll
        for (int k = 0; k < 16; k++) {
            float4 av = *(const float4*)&Ws[k][ty * 4];
            float4 bv = *(const float4*)&Xs[k][tx * 4];
            unsigned long long b0 = pack2(bv.x, bv.y), b1 = pack2(bv.z, bv.w);
            unsigned long long a0 = pack2(av.x, av.x), a1 = pack2(av.y, av.y);
            unsigned long long a2 = pack2(av.z, av.z), a3 = pack2(av.w, av.w);
            fma2(acc[0][0], a0, b0); fma2(acc[0][1], a0, b1);
            fma2(acc[1][0], a1, b0); fma2(acc[1][1], a1, b1);
            fma2(acc[2][0], a2, b0); fma2(acc[2][1], a2, b1);
            fma2(acc[3][0], a3, b0); fma2(acc[3][1], a3, b1);
        }
        __syncthreads();
    }

    float* out = g_qkv + ((size_t)b * OC + o0) * HWSZ + hw0;
#pragma unroll
    for (int i = 0; i < 4; i++) {
        float2 lo = unp2(acc[i][0]), hi = unp2(acc[i][1]);
        *(float4*)&out[(size_t)(ty * 4 + i) * HWSZ + tx * 4] =
            make_float4(lo.x, lo.y, hi.x, hi.y);
    }
}

// ============================================================
// K2: 2x2 maxpool of k,v channels of qkv into g_k, g_v
// ============================================================
__global__ void __launch_bounds__(256) k_pool() {
    int idx = blockIdx.x * 256 + threadIdx.x;
    const int total = BB * (DQ + DV) * MM;
    if (idx >= total) return;
    int m  = idx & (MM - 1);
    int ch = (idx >> 10) % (DQ + DV);
    int b  = idx / ((DQ + DV) * MM);
    int y = m >> 5, x = m & 31;
    // source row in qkv: k part rows [DQ,2DQ), v part rows [2DQ,OC) -> both = DQ + ch
    const float* src = g_qkv + ((size_t)b * OC + DQ + ch) * HWSZ + (y * 2) * WW + x * 2;
    float v = fmaxf(fmaxf(src[0], src[1]), fmaxf(src[WW], src[WW + 1]));
    if (ch < DQ) g_k[((size_t)b * DQ + ch) * MM + m] = v;
    else         g_v[((size_t)b * DV + (ch - DQ)) * MM + m] = v;
}

// ============================================================
// K3: fused attention per (batch, 64-query tile)
//   S = q^T k, E = exp(S) (no max-subtract; |S| small), O = E V^T, O /= rowsum
// SMEM: Qs[32][64], Ks[32][1024], Vs[64][132], Es[64][68], rsum[64]
// ============================================================
#define SM_QS 0
#define SM_KS (32 * 64)
#define SM_VS (SM_KS + 32 * 1024)
#define SM_ES (SM_VS + 64 * 132)
#define SM_RS (SM_ES + 64 * 68)
#define SM_ATTN_BYTES ((SM_RS + 64) * 4)

__global__ void __launch_bounds__(256, 1) k_attn() {
    extern __shared__ float sm[];
    float* Qs   = sm + SM_QS;
    float* Ks   = sm + SM_KS;
    float* Vs   = sm + SM_VS;   // [m_local][d], stride 132
    float* Es   = sm + SM_ES;   // [n_local][m_local], stride 68
    float* rsum = sm + SM_RS;

    const int b   = blockIdx.y;
    const int n0g = blockIdx.x * 64;
    const int tid = threadIdx.x;
    const int tx  = tid & 15;
    const int ty  = tid >> 4;

    // Load Q tile [32 d][64 n]
    for (int e = tid; e < 32 * 64; e += 256) {
        int d = e >> 6, n = e & 63;
        Qs[d * 64 + n] = g_qkv[((size_t)b * OC + d) * HWSZ + n0g + n];
    }
    // Load full K [32][1024]
    {
        const float4* src = (const float4*)(g_k + (size_t)b * DQ * MM);
        float4* dst = (float4*)Ks;
        for (int e = tid; e < (32 * 1024) / 4; e += 256) dst[e] = src[e];
    }
    if (tid < 64) rsum[tid] = 0.0f;

    unsigned long long o2[4][4];   // [n_i][d_pair]: d = tx*8 + 2p
#pragma unroll
    for (int i = 0; i < 4; i++)
#pragma unroll
        for (int p = 0; p < 4; p++) o2[i][p] = 0ull;
    float rs[4] = {0.f, 0.f, 0.f, 0.f};

    __syncthreads();

    for (int mt = 0; mt < 16; mt++) {
        const int mb = mt * 64;
        // Load V tile [64 m][128 d] transposed, stride 132
        for (int e = tid; e < 64 * 128; e += 256) {
            int d = e >> 6, m = e & 63;
            Vs[m * 132 + d] = g_v[((size_t)b * DV + d) * MM + mb + m];
        }
        // S tile: [n=ty*4+i][m=tx*4+j]
        unsigned long long s2[4][2];
#pragma unroll
        for (int i = 0; i < 4; i++) { s2[i][0] = 0ull; s2[i][1] = 0ull; }
#pragma unroll
        for (int d = 0; d < 32; d++) {
            float4 qv = *(const float4*)&Qs[d * 64 + ty * 4];
            float4 kv = *(const float4*)&Ks[d * 1024 + mb + tx * 4];
            unsigned long long k0 = pack2(kv.x, kv.y), k1 = pack2(kv.z, kv.w);
            unsigned long long q0 = pack2(qv.x, qv.x), q1 = pack2(qv.y, qv.y);
            unsigned long long q2 = pack2(qv.z, qv.z), q3 = pack2(qv.w, qv.w);
            fma2(s2[0][0], q0, k0); fma2(s2[0][1], q0, k1);
            fma2(s2[1][0], q1, k0); fma2(s2[1][1], q1, k1);
            fma2(s2[2][0], q2, k0); fma2(s2[2][1], q2, k1);
            fma2(s2[3][0], q3, k0); fma2(s2[3][1], q3, k1);
        }
        float ev[4][4];
#pragma unroll
        for (int i = 0; i < 4; i++) {
            float2 f0 = unp2(s2[i][0]), f1 = unp2(s2[i][1]);
            ev[i][0] = __expf(f0.x); ev[i][1] = __expf(f0.y);
            ev[i][2] = __expf(f1.x); ev[i][3] = __expf(f1.y);
            rs[i] += (ev[i][0] + ev[i][1]) + (ev[i][2] + ev[i][3]);
        }
        __syncthreads();   // V tile complete; previous Es consumers done
#pragma unroll
        for (int i = 0; i < 4; i++)
            *(float4*)&Es[(ty * 4 + i) * 68 + tx * 4] =
                make_float4(ev[i][0], ev[i][1], ev[i][2], ev[i][3]);
        __syncthreads();
        // PV: O[n][d] += E[n][kk] * V[kk][d]
#pragma unroll 8
        for (int kk = 0; kk < 64; kk++) {
            ulonglong2 va = *(const ulonglong2*)&Vs[kk * 132 + tx * 8];
            ulonglong2 vb = *(const ulonglong2*)&Vs[kk * 132 + tx * 8 + 4];
            float e0 = Es[(ty * 4 + 0) * 68 + kk];
            float e1 = Es[(ty * 4 + 1) * 68 + kk];
            float e2 = Es[(ty * 4 + 2) * 68 + kk];
            float e3 = Es[(ty * 4 + 3) * 68 + kk];
            unsigned long long p0 = pack2(e0, e0), p1 = pack2(e1, e1);
            unsigned long long p2 = pack2(e2, e2), p3 = pack2(e3, e3);
            fma2(o2[0][0], p0, va.x); fma2(o2[0][1], p0, va.y);
            fma2(o2[0][2], p0, vb.x); fma2(o2[0][3], p0, vb.y);
            fma2(o2[1][0], p1, va.x); fma2(o2[1][1], p1, va.y);
            fma2(o2[1][2], p1, vb.x); fma2(o2[1][3], p1, vb.y);
            fma2(o2[2][0], p2, va.x); fma2(o2[2][1], p2, va.y);
            fma2(o2[2][2], p2, vb.x); fma2(o2[2][3], p2, vb.y);
            fma2(o2[3][0], p3, va.x); fma2(o2[3][1], p3, va.y);
            fma2(o2[3][2], p3, vb.x); fma2(o2[3][3], p3, vb.y);
        }
        __syncthreads();   // protect Vs/Es before next tile's overwrite
    }

    // Row sums -> normalize
#pragma unroll
    for (int i = 0; i < 4; i++) atomicAdd(&rsum[ty * 4 + i], rs[i]);
    __syncthreads();
    float inv[4];
#pragma unroll
    for (int i = 0; i < 4; i++) inv[i] = 1.0f / rsum[ty * 4 + i];

    // Stage normalized O into Vs region as [n][d], then write coalesced
    float* Os = Vs;
#pragma unroll
    for (int i = 0; i < 4; i++) {
        int n = ty * 4 + i;
#pragma unroll
        for (int p = 0; p < 4; p++) {
            float2 f = unp2(o2[i][p]);
            int d = tx * 8 + p * 2;
            *(float2*)&Os[n * 132 + d] = make_float2(f.x * inv[i], f.y * inv[i]);
        }
    }
    __syncthreads();
    for (int e = tid; e < DV * 64; e += 256) {
        int d = e >> 6, n = e & 63;
        g_ao[((size_t)b * DV + d) * HWSZ + n0g + n] = Os[n * 132 + d];
    }
}

// ============================================================
// K4: out = imgs + scale * (w_out @ attn_out)   [256x128]@[128x4096]
// ============================================================
__global__ void __launch_bounds__(256) k_out(const float* __restrict__ imgs,
                                             const float* __restrict__ wout,
                                             const float* __restrict__ scale_p,
                                             float* __restrict__ out) {
    __shared__ float Ws[16][68];   // [d_local][c_local]
    __shared__ float As[16][64];   // [d_local][hw_local]

    const int b   = blockIdx.z;
    const int c0  = blockIdx.y * 64;
    const int hw0 = blockIdx.x * 64;
    const int tid = threadIdx.x;
    const int tx  = tid & 15;
    const int ty  = tid >> 4;

    unsigned long long acc[4][2];
#pragma unroll
    for (int i = 0; i < 4; i++) { acc[i][0] = 0ull; acc[i][1] = 0ull; }

    for (int kk = 0; kk < DV; kk += 16) {
#pragma unroll
        for (int e = tid; e < 1024; e += 256) {
            int cl = e >> 4, dl = e & 15;
            Ws[dl][cl] = wout[(size_t)(c0 + cl) * DV + kk + dl];
        }
#pragma unroll
        for (int e = tid; e < 1024; e += 256) {
            int dl = e >> 6, hl = e & 63;
            As[dl][hl] = g_ao[((size_t)b * DV + kk + dl) * HWSZ + hw0 + hl];
        }
        __syncthreads();
#pragma unroll
        for (int k = 0; k < 16; k++) {
            float4 av = *(const float4*)&Ws[k][ty * 4];
            float4 bv = *(const float4*)&As[k][tx * 4];
            unsigned long long b0 = pack2(bv.x, bv.y), b1 = pack2(bv.z, bv.w);
            unsigned long long a0 = pack2(av.x, av.x), a1 = pack2(av.y, av.y);
            unsigned long long a2 = pack2(av.z, av.z), a3 = pack2(av.w, av.w);
            fma2(acc[0][0], a0, b0); fma2(acc[0][1], a0, b1);
            fma2(acc[1][0], a1, b0); fma2(acc[1][1], a1, b1);
            fma2(acc[2][0], a2, b0); fma2(acc[2][1], a2, b1);
            fma2(acc[3][0], a3, b0); fma2(acc[3][1], a3, b1);
        }
        __syncthreads();
    }

    const float s = *scale_p;
    const size_t base = ((size_t)b * CC + c0 + ty * 4) * HWSZ + hw0 + tx * 4;
#pragma unroll
    for (int i = 0; i < 4; i++) {
        float2 lo = unp2(acc[i][0]), hi = unp2(acc[i][1]);
        size_t idx = base + (size_t)i * HWSZ;
        float4 im = *(const float4*)&imgs[idx];
        *(float4*)&out[idx] = make_float4(im.x + s * lo.x, im.y + s * lo.y,
                                          im.z + s * hi.x, im.w + s * hi.y);
    }
}

// ============================================================
extern "C" void kernel_launch(void* const* d_in, const int* in_sizes, int n_in,
                              void* d_out, int out_size) {
    const float* imgs  = (const float*)d_in[0];
    const float* wqkv  = (const float*)d_in[1];
    const float* wout  = (const float*)d_in[2];
    const float* scale = (const float*)d_in[3];
    float* out = (float*)d_out;

    cudaFuncSetAttribute(k_attn, cudaFuncAttributeMaxDynamicSharedMemorySize,
                         SM_ATTN_BYTES);

    k_qkv<<<dim3(64, 3, 16), 256>>>(imgs, wqkv);

    const int pool_total = BB * (DQ + DV) * MM;
    k_pool<<<(pool_total + 255) / 256, 256>>>();

    k_attn<<<dim3(64, 16), 256, SM_ATTN_BYTES>>>();

    k_out<<<dim3(64, 4, 16), 256>>>(imgs, wout, scale, out);
}

// round 10
// speedup vs baseline: 1.9967x; 1.9967x over previous
#include <cuda_runtime.h>
#include <cstdint>

// Problem constants
#define BB   16
#define CC   256
#define HH   64
#define WW   64
#define HWSZ 4096     // H*W
#define DQ   32       // C/8
#define DV   128      // C/2
#define OC   192      // 2*DQ + DV
#define MM   1024     // pooled spatial (32*32)

// Scratch (device globals: allocation-free rule)
__device__ float g_qkv[BB * OC * HWSZ];   // full qkv fp32
__device__ float g_k[BB * DQ * MM];       // pooled K fp32 [b][d][m]
__device__ float g_v[BB * DV * MM];       // pooled V fp32 [b][d][m]
__device__ float g_ao[BB * DV * HWSZ];    // attention output [b][d][n]

// ---- tf32 mma.sync helpers (baseline ISA, works on plain sm_103 target) ----
__device__ __forceinline__ uint32_t f2tf32(float f) {
    uint32_t r;
    asm("cvt.rna.tf32.f32 %0, %1;" : "=r"(r) : "f"(f));
    return r;
}
// D += A(16x8,row) * B(8x8,col), tf32 in, f32 accum
__device__ __forceinline__ void mma_tf32(float* c, const uint32_t* a, const uint32_t* b) {
    asm volatile("mma.sync.aligned.m16n8k8.row.col.f32.tf32.tf32.f32 "
        "{%0,%1,%2,%3}, {%4,%5,%6,%7}, {%8,%9}, {%0,%1,%2,%3};"
        : "+f"(c[0]), "+f"(c[1]), "+f"(c[2]), "+f"(c[3])
        : "r"(a[0]), "r"(a[1]), "r"(a[2]), "r"(a[3]), "r"(b[0]), "r"(b[1]));
}

// One shared extern dynamic-smem symbol for all kernels
extern __shared__ uint32_t dynsm[];

// ============================================================
// K1: qkv = w_qkv @ imgs  per batch: M=192(o) N=4096(hw) K=256(c)
// CTA: 256 thr (8 warps, 2m x 4n), tile 64 x 256. A whole-K in SMEM.
// ============================================================
#define QKV_SB_OFF (64 * 260)
#define QKV_SMEM_BYTES ((64 * 260 + 32 * 264) * 4)   // 100352

__global__ void __launch_bounds__(256) k_qkv_mma(const float* __restrict__ imgs,
                                                 const float* __restrict__ wq) {
    uint32_t* sA = dynsm;                 // [64][260]
    uint32_t* sB = dynsm + QKV_SB_OFF;    // [32][264]
    const int b  = blockIdx.z;
    const int o0 = blockIdx.y * 64;
    const int n0 = blockIdx.x * 256;
    const int tid = threadIdx.x, lane = tid & 31, wid = tid >> 5;
    const int wm = (wid >> 2) * 32;       // warp row base (0/32)
    const int wn = (wid & 3) * 64;        // warp col base
    const float* X = imgs + (size_t)b * CC * HWSZ;

    for (int e = tid; e < 64 * 256; e += 256) {
        int o = e >> 8, c = e & 255;
        sA[o * 260 + c] = f2tf32(wq[(size_t)(o0 + o) * CC + c]);
    }

    float acc[2][8][4];
#pragma unroll
    for (int mf = 0; mf < 2; mf++)
#pragma unroll
        for (int nf = 0; nf < 8; nf++)
#pragma unroll
            for (int j = 0; j < 4; j++) acc[mf][nf][j] = 0.0f;

    for (int kc = 0; kc < CC; kc += 32) {
        __syncthreads();
        for (int e = tid; e < 32 * 256; e += 256) {
            int c = e >> 8, n = e & 255;
            sB[c * 264 + n] = f2tf32(X[(size_t)(kc + c) * HWSZ + n0 + n]);
        }
        __syncthreads();
#pragma unroll
        for (int k8 = 0; k8 < 32; k8 += 8) {
            uint32_t a[2][4];
            const int ar  = wm + (lane >> 2);
            const int acd = kc + k8 + (lane & 3);
#pragma unroll
            for (int mf = 0; mf < 2; mf++) {
                int r = ar + mf * 16;
                a[mf][0] = sA[r * 260 + acd];
                a[mf][1] = sA[(r + 8) * 260 + acd];
                a[mf][2] = sA[r * 260 + acd + 4];
                a[mf][3] = sA[(r + 8) * 260 + acd + 4];
            }
#pragma unroll
            for (int nf = 0; nf < 8; nf++) {
                int bn = wn + nf * 8 + (lane >> 2);
                uint32_t bf[2];
                bf[0] = sB[(k8 + (lane & 3)) * 264 + bn];
                bf[1] = sB[(k8 + 4 + (lane & 3)) * 264 + bn];
                mma_tf32(acc[0][nf], a[0], bf);
                mma_tf32(acc[1][nf], a[1], bf);
            }
        }
    }

    float* out = g_qkv + ((size_t)b * OC + o0) * HWSZ + n0;
#pragma unroll
    for (int mf = 0; mf < 2; mf++)
#pragma unroll
        for (int nf = 0; nf < 8; nf++) {
            int row = wm + mf * 16 + (lane >> 2);
            int col = wn + nf * 8 + 2 * (lane & 3);
            *(float2*)&out[(size_t)row * HWSZ + col] =
                make_float2(acc[mf][nf][0], acc[mf][nf][1]);
            *(float2*)&out[(size_t)(row + 8) * HWSZ + col] =
                make_float2(acc[mf][nf][2], acc[mf][nf][3]);
        }
}

// ============================================================
// K2: 2x2 maxpool (unchanged)
// ============================================================
__global__ void __launch_bounds__(256) k_pool() {
    int idx = blockIdx.x * 256 + threadIdx.x;
    const int total = BB * (DQ + DV) * MM;
    if (idx >= total) return;
    int m  = idx & (MM - 1);
    int ch = (idx >> 10) % (DQ + DV);
    int b  = idx / ((DQ + DV) * MM);
    int y = m >> 5, x = m & 31;
    const float* src = g_qkv + ((size_t)b * OC + DQ + ch) * HWSZ + (y * 2) * WW + x * 2;
    float v = fmaxf(fmaxf(src[0], src[1]), fmaxf(src[WW], src[WW + 1]));
    if (ch < DQ) g_k[((size_t)b * DQ + ch) * MM + m] = v;
    else         g_v[((size_t)b * DV + (ch - DQ)) * MM + m] = v;
}

// ============================================================
// K3: flash attention with tf32 mma.sync.
// CTA: 256 thr = 8 warps x 16 q rows -> 128-query tile. grid (32, 16).
// ============================================================
#define SATT_Q  (32 * 1032)
#define SATT_V  (SATT_Q + 32 * 136)
#define SATT_E  (SATT_V + 128 * 68)
#define SATT_SMEM_BYTES ((SATT_E + 128 * 68) * 4)    // 219136

__global__ void __launch_bounds__(256, 1) k_attn_mma() {
    uint32_t* sK = dynsm;
    uint32_t* sQ = dynsm + SATT_Q;
    uint32_t* sV = dynsm + SATT_V;
    uint32_t* sE = dynsm + SATT_E;

    const int b   = blockIdx.y;
    const int n0  = blockIdx.x * 128;
    const int tid = threadIdx.x, lane = tid & 31, wid = tid >> 5;
    const int qb  = wid * 16;            // this warp's query-row base
    const int lr  = lane >> 2;           // 0..7
    const int lc  = lane & 3;            // 0..3

    // Load Q [32 d][128 n] and full K [32 d][1024 m] as tf32
    for (int e = tid; e < 32 * 128; e += 256) {
        int d = e >> 7, n = e & 127;
        sQ[d * 136 + n] = f2tf32(g_qkv[((size_t)b * OC + d) * HWSZ + n0 + n]);
    }
    for (int e = tid; e < 32 * 1024; e += 256) {
        int d = e >> 10, m = e & 1023;
        sK[d * 1032 + m] = f2tf32(g_k[((size_t)b * DQ + d) * MM + m]);
    }
    __syncthreads();

    // Preload Q A-fragments (constant across all key tiles): 4 k8-steps
    uint32_t qa[4][4];
#pragma unroll
    for (int ks = 0; ks < 4; ks++) {
        int d = ks * 8 + lc;
        qa[ks][0] = sQ[d * 136 + qb + lr];
        qa[ks][1] = sQ[d * 136 + qb + lr + 8];
        qa[ks][2] = sQ[(d + 4) * 136 + qb + lr];
        qa[ks][3] = sQ[(d + 4) * 136 + qb + lr + 8];
    }

    float oacc[16][4];
#pragma unroll
    for (int nf = 0; nf < 16; nf++)
#pragma unroll
        for (int j = 0; j < 4; j++) oacc[nf][j] = 0.0f;
    float rs0 = 0.0f, rs1 = 0.0f;

    for (int mt = 0; mt < 16; mt++) {
        const int mb = mt * 64;
        __syncthreads();   // prev iteration's PV (sE/sV readers) done
        // Load V chunk [128 d][64 m]
        for (int e = tid; e < 128 * 64; e += 256) {
            int d = e >> 6, m = e & 63;
            sV[d * 68 + m] = f2tf32(g_v[((size_t)b * DV + d) * MM + mb + m]);
        }
        // S = Q @ K_tile^T : per warp 16 q x 64 m
        float sf[8][4];
#pragma unroll
        for (int nf = 0; nf < 8; nf++)
#pragma unroll
            for (int j = 0; j < 4; j++) sf[nf][j] = 0.0f;
#pragma unroll
        for (int ks = 0; ks < 4; ks++) {
            const int dr0 = (ks * 8 + lc) * 1032;
            const int dr1 = (ks * 8 + 4 + lc) * 1032;
#pragma unroll
            for (int nf = 0; nf < 8; nf++) {
                int mcol = mb + nf * 8 + lr;
                uint32_t bf[2] = { sK[dr0 + mcol], sK[dr1 + mcol] };
                mma_tf32(sf[nf], qa[ks], bf);
            }
        }
        // exp + rowsum; store E as tf32 bits
#pragma unroll
        for (int nf = 0; nf < 8; nf++) {
            float e0 = __expf(sf[nf][0]);
            float e1 = __expf(sf[nf][1]);
            float e2 = __expf(sf[nf][2]);
            float e3 = __expf(sf[nf][3]);
            rs0 += e0 + e1;
            rs1 += e2 + e3;
            int col = nf * 8 + 2 * lc;
            uint32_t* p0 = &sE[(qb + lr) * 68 + col];
            uint32_t* p1 = &sE[(qb + lr + 8) * 68 + col];
            p0[0] = f2tf32(e0); p0[1] = f2tf32(e1);
            p1[0] = f2tf32(e2); p1[1] = f2tf32(e3);
        }
        __syncthreads();   // sV + sE complete for all warps
        // O += E @ V^T : per warp 16 q x 128 d, k = 64 m (8 k8-steps)
#pragma unroll
        for (int ks = 0; ks < 8; ks++) {
            uint32_t ea[4];
            int m = ks * 8 + lc;
            ea[0] = sE[(qb + lr) * 68 + m];
            ea[1] = sE[(qb + lr + 8) * 68 + m];
            ea[2] = sE[(qb + lr) * 68 + m + 4];
            ea[3] = sE[(qb + lr + 8) * 68 + m + 4];
#pragma unroll
            for (int nf = 0; nf < 16; nf++) {
                int drow = (nf * 8 + lr) * 68;
                uint32_t bf[2] = { sV[drow + m], sV[drow + m + 4] };
                mma_tf32(oacc[nf], ea, bf);
            }
        }
    }

    // Row-sum reduction across the 4 column-owner lanes (quad butterfly)
    rs0 += __shfl_xor_sync(0xffffffffu, rs0, 1);
    rs0 += __shfl_xor_sync(0xffffffffu, rs0, 2);
    rs1 += __shfl_xor_sync(0xffffffffu, rs1, 1);
    rs1 += __shfl_xor_sync(0xffffffffu, rs1, 2);
    const float inv0 = 1.0f / rs0, inv1 = 1.0f / rs1;

    // Normalize + stage O[q][d] (reuse sK region, stride 133: banks 5q+d,
    // conflict-free). Stride 133 is ODD -> word index parity varies with q, so
    // these MUST be scalar 4-byte stores (float2 here trapped: misaligned).
    float* Os = (float*)dynsm;
    __syncthreads();   // everyone past last sK read
#pragma unroll
    for (int nf = 0; nf < 16; nf++) {
        int col = nf * 8 + 2 * lc;
        float* q0 = &Os[(qb + lr) * 133 + col];
        float* q1 = &Os[(qb + lr + 8) * 133 + col];
        q0[0] = oacc[nf][0] * inv0;
        q0[1] = oacc[nf][1] * inv0;
        q1[0] = oacc[nf][2] * inv1;
        q1[1] = oacc[nf][3] * inv1;
    }
    __syncthreads();
    for (int e = tid; e < DV * 128; e += 256) {
        int d = e >> 7, q = e & 127;
        g_ao[((size_t)b * DV + d) * HWSZ + n0 + q] = Os[q * 133 + d];
    }
}

// ============================================================
// K4: out = imgs + scale * (w_out @ attn_out)  M=256(c) N=4096 K=128(d)
// ============================================================
#define OUT_SB_OFF (64 * 132)
#define OUT_SMEM_BYTES ((64 * 132 + 32 * 264) * 4)   // 67584

__global__ void __launch_bounds__(256) k_out_mma(const float* __restrict__ imgs,
                                                 const float* __restrict__ wout,
                                                 const float* __restrict__ scale_p,
                                                 float* __restrict__ out) {
    uint32_t* sA = dynsm;                 // [64][132]
    uint32_t* sB = dynsm + OUT_SB_OFF;    // [32][264]
    const int b  = blockIdx.z;
    const int c0 = blockIdx.y * 64;
    const int n0 = blockIdx.x * 256;
    const int tid = threadIdx.x, lane = tid & 31, wid = tid >> 5;
    const int wm = (wid >> 2) * 32;
    const int wn = (wid & 3) * 64;

    for (int e = tid; e < 64 * 128; e += 256) {
        int c = e >> 7, d = e & 127;
        sA[c * 132 + d] = f2tf32(wout[(size_t)(c0 + c) * DV + d]);
    }

    float acc[2][8][4];
#pragma unroll
    for (int mf = 0; mf < 2; mf++)
#pragma unroll
        for (int nf = 0; nf < 8; nf++)
#pragma unroll
            for (int j = 0; j < 4; j++) acc[mf][nf][j] = 0.0f;

    for (int kc = 0; kc < DV; kc += 32) {
        __syncthreads();
        for (int e = tid; e < 32 * 256; e += 256) {
            int d = e >> 8, n = e & 255;
            sB[d * 264 + n] = f2tf32(g_ao[((size_t)b * DV + kc + d) * HWSZ + n0 + n]);
        }
        __syncthreads();
#pragma unroll
        for (int k8 = 0; k8 < 32; k8 += 8) {
            uint32_t a[2][4];
            const int ar  = wm + (lane >> 2);
            const int acd = kc + k8 + (lane & 3);
#pragma unroll
            for (int mf = 0; mf < 2; mf++) {
                int r = ar + mf * 16;
                a[mf][0] = sA[r * 132 + acd];
                a[mf][1] = sA[(r + 8) * 132 + acd];
                a[mf][2] = sA[r * 132 + acd + 4];
                a[mf][3] = sA[(r + 8) * 132 + acd + 4];
            }
#pragma unroll
            for (int nf = 0; nf < 8; nf++) {
                int bn = wn + nf * 8 + (lane >> 2);
                uint32_t bf[2];
                bf[0] = sB[(k8 + (lane & 3)) * 264 + bn];
                bf[1] = sB[(k8 + 4 + (lane & 3)) * 264 + bn];
                mma_tf32(acc[0][nf], a[0], bf);
                mma_tf32(acc[1][nf], a[1], bf);
            }
        }
    }

    const float s = *scale_p;
#pragma unroll
    for (int mf = 0; mf < 2; mf++)
#pragma unroll
        for (int nf = 0; nf < 8; nf++) {
            int row = c0 + wm + mf * 16 + (lane >> 2);
            int col = wn + nf * 8 + 2 * (lane & 3);
            size_t i0 = ((size_t)b * CC + row) * HWSZ + n0 + col;
            size_t i1 = ((size_t)b * CC + row + 8) * HWSZ + n0 + col;
            float2 m0 = *(const float2*)&imgs[i0];
            float2 m1 = *(const float2*)&imgs[i1];
            *(float2*)&out[i0] = make_float2(m0.x + s * acc[mf][nf][0],
                                             m0.y + s * acc[mf][nf][1]);
            *(float2*)&out[i1] = make_float2(m1.x + s * acc[mf][nf][2],
                                             m1.y + s * acc[mf][nf][3]);
        }
}

// ============================================================
extern "C" void kernel_launch(void* const* d_in, const int* in_sizes, int n_in,
                              void* d_out, int out_size) {
    const float* imgs  = (const float*)d_in[0];
    const float* wqkv  = (const float*)d_in[1];
    const float* wout  = (const float*)d_in[2];
    const float* scale = (const float*)d_in[3];
    float* out = (float*)d_out;

    cudaFuncSetAttribute(k_qkv_mma,  cudaFuncAttributeMaxDynamicSharedMemorySize, QKV_SMEM_BYTES);
    cudaFuncSetAttribute(k_attn_mma, cudaFuncAttributeMaxDynamicSharedMemorySize, SATT_SMEM_BYTES);
    cudaFuncSetAttribute(k_out_mma,  cudaFuncAttributeMaxDynamicSharedMemorySize, OUT_SMEM_BYTES);

    k_qkv_mma<<<dim3(16, 3, 16), 256, QKV_SMEM_BYTES>>>(imgs, wqkv);

    const int pool_total = BB * (DQ + DV) * MM;
    k_pool<<<(pool_total + 255) / 256, 256>>>();

    k_attn_mma<<<dim3(32, 16), 256, SATT_SMEM_BYTES>>>();

    k_out_mma<<<dim3(16, 4, 16), 256, OUT_SMEM_BYTES>>>(imgs, wout, scale, out);
}

// round 11
// speedup vs baseline: 3.9791x; 1.9928x over previous
#include <cuda_runtime.h>
#include <cstdint>

// Problem constants
#define BB   16
#define CC   256
#define HH   64
#define WW   64
#define HWSZ 4096     // H*W
#define DQ   32       // C/8
#define DV   128      // C/2
#define OC   192      // 2*DQ + DV
#define MM   1024     // pooled spatial (32*32)

// Scratch (device globals: allocation-free rule)
__device__ float g_qkv[BB * OC * HWSZ];   // full qkv fp32
__device__ float g_k[BB * DQ * MM];       // pooled K fp32 [b][d][m]
__device__ float g_v[BB * DV * MM];       // pooled V fp32 [b][d][m]
__device__ float g_ao[BB * DV * HWSZ];    // attention output [b][d][n]

// ---- tf32 mma.sync. NOTE: operands carry RAW fp32 bits — HMMA.TF32 reads
// the tf32 subset (truncation instead of RNE). Saves all cvt work and lets
// cp.async feed SMEM directly from gmem.
__device__ __forceinline__ void mma_tf32(float* c, const uint32_t* a, const uint32_t* b) {
    asm volatile("mma.sync.aligned.m16n8k8.row.col.f32.tf32.tf32.f32 "
        "{%0,%1,%2,%3}, {%4,%5,%6,%7}, {%8,%9}, {%0,%1,%2,%3};"
        : "+f"(c[0]), "+f"(c[1]), "+f"(c[2]), "+f"(c[3])
        : "r"(a[0]), "r"(a[1]), "r"(a[2]), "r"(a[3]), "r"(b[0]), "r"(b[1]));
}

// ---- cp.async helpers (baseline ISA, Ampere+) ----
__device__ __forceinline__ void cp16(void* dst, const void* src) {
    uint32_t d = (uint32_t)__cvta_generic_to_shared(dst);
    asm volatile("cp.async.cg.shared.global [%0], [%1], 16;" :: "r"(d), "l"(src) : "memory");
}
#define CP_COMMIT() asm volatile("cp.async.commit_group;" ::: "memory")
#define CP_WAIT0()  asm volatile("cp.async.wait_group 0;" ::: "memory")
#define CP_WAIT1()  asm volatile("cp.async.wait_group 1;" ::: "memory")

// One shared extern dynamic-smem symbol for all kernels
extern __shared__ uint32_t dynsm[];

// ============================================================
// K1: qkv = w_qkv @ imgs  per batch: M=192(o) N=4096(hw) K=256(c)
// CTA: 256 thr (8 warps, 2m x 4n), tile 64 x 256.
// Double-buffered cp.async k-chunks: sA[2][64][36], sB[2][32][264].
// 86016 B smem -> 2 CTAs/SM.
// ============================================================
#define G_SA(i) ((i) * 2304)              // 64*36
#define G_SB(i) (4608 + (i) * 8448)       // 32*264
#define GEMM_SMEM_BYTES ((4608 + 2 * 8448) * 4)   // 86016

__global__ void __launch_bounds__(256) k_qkv_mma(const float* __restrict__ imgs,
                                                 const float* __restrict__ wq) {
    const int b  = blockIdx.z;
    const int o0 = blockIdx.y * 64;
    const int n0 = blockIdx.x * 256;
    const int tid = threadIdx.x, lane = tid & 31, wid = tid >> 5;
    const int wm = (wid >> 2) * 32;       // warp row base (0/32)
    const int wn = (wid & 3) * 64;        // warp col base
    const float* X = imgs + (size_t)b * CC * HWSZ;

    // prefetch chunk kc into buffer ibuf (A: 64x32, B: 32x256)
    auto prefetch = [&](int ibuf, int kc) {
        uint32_t* sA = dynsm + G_SA(ibuf);
        uint32_t* sB = dynsm + G_SB(ibuf);
#pragma unroll
        for (int it = 0; it < 2; it++) {            // A: 512 float4
            int u = tid + it * 256;
            int o = u >> 3, cv = u & 7;
            cp16(&sA[o * 36 + cv * 4], wq + (size_t)(o0 + o) * CC + kc + cv * 4);
        }
#pragma unroll
        for (int it = 0; it < 8; it++) {            // B: 2048 float4
            int u = tid + it * 256;
            int c = u >> 6, nv = u & 63;
            cp16(&sB[c * 264 + nv * 4], X + (size_t)(kc + c) * HWSZ + n0 + nv * 4);
        }
        CP_COMMIT();
    };

    float acc[2][8][4];
#pragma unroll
    for (int mf = 0; mf < 2; mf++)
#pragma unroll
        for (int nf = 0; nf < 8; nf++)
#pragma unroll
            for (int j = 0; j < 4; j++) acc[mf][nf][j] = 0.0f;

    prefetch(0, 0);
    for (int ic = 0; ic < 8; ic++) {
        if (ic + 1 < 8) { prefetch((ic + 1) & 1, (ic + 1) * 32); CP_WAIT1(); }
        else            { CP_WAIT0(); }
        __syncthreads();
        const uint32_t* sA = dynsm + G_SA(ic & 1);
        const uint32_t* sB = dynsm + G_SB(ic & 1);
#pragma unroll
        for (int k8 = 0; k8 < 32; k8 += 8) {
            uint32_t a[2][4];
            const int ar = wm + (lane >> 2);
            const int ac = k8 + (lane & 3);
#pragma unroll
            for (int mf = 0; mf < 2; mf++) {
                int r = ar + mf * 16;
                a[mf][0] = sA[r * 36 + ac];
                a[mf][1] = sA[(r + 8) * 36 + ac];
                a[mf][2] = sA[r * 36 + ac + 4];
                a[mf][3] = sA[(r + 8) * 36 + ac + 4];
            }
#pragma unroll
            for (int nf = 0; nf < 8; nf++) {
                int bn = wn + nf * 8 + (lane >> 2);
                uint32_t bf[2];
                bf[0] = sB[(k8 + (lane & 3)) * 264 + bn];
                bf[1] = sB[(k8 + 4 + (lane & 3)) * 264 + bn];
                mma_tf32(acc[0][nf], a[0], bf);
                mma_tf32(acc[1][nf], a[1], bf);
            }
        }
        __syncthreads();   // compute done before next prefetch overwrites other buf
    }

    float* out = g_qkv + ((size_t)b * OC + o0) * HWSZ + n0;
#pragma unroll
    for (int mf = 0; mf < 2; mf++)
#pragma unroll
        for (int nf = 0; nf < 8; nf++) {
            int row = wm + mf * 16 + (lane >> 2);
            int col = wn + nf * 8 + 2 * (lane & 3);
            *(float2*)&out[(size_t)row * HWSZ + col] =
                make_float2(acc[mf][nf][0], acc[mf][nf][1]);
            *(float2*)&out[(size_t)(row + 8) * HWSZ + col] =
                make_float2(acc[mf][nf][2], acc[mf][nf][3]);
        }
}

// ============================================================
// K2: 2x2 maxpool (unchanged)
// ============================================================
__global__ void __launch_bounds__(256) k_pool() {
    int idx = blockIdx.x * 256 + threadIdx.x;
    const int total = BB * (DQ + DV) * MM;
    if (idx >= total) return;
    int m  = idx & (MM - 1);
    int ch = (idx >> 10) % (DQ + DV);
    int b  = idx / ((DQ + DV) * MM);
    int y = m >> 5, x = m & 31;
    const float* src = g_qkv + ((size_t)b * OC + DQ + ch) * HWSZ + (y * 2) * WW + x * 2;
    float v = fmaxf(fmaxf(src[0], src[1]), fmaxf(src[WW], src[WW + 1]));
    if (ch < DQ) g_k[((size_t)b * DQ + ch) * MM + m] = v;
    else         g_v[((size_t)b * DV + (ch - DQ)) * MM + m] = v;
}

// ============================================================
// K3: flash attention with tf32 mma.sync.
// CTA: 256 thr = 8 warps x 16 q rows -> 128-query tile. grid (32, 16).
// V tile load via cp.async, overlapped with S-mma + softmax.
// ============================================================
#define SATT_Q  (32 * 1032)
#define SATT_V  (SATT_Q + 32 * 136)
#define SATT_E  (SATT_V + 128 * 68)
#define SATT_SMEM_BYTES ((SATT_E + 128 * 68) * 4)    // 219136

__global__ void __launch_bounds__(256, 1) k_attn_mma() {
    uint32_t* sK = dynsm;
    uint32_t* sQ = dynsm + SATT_Q;
    uint32_t* sV = dynsm + SATT_V;
    uint32_t* sE = dynsm + SATT_E;

    const int b   = blockIdx.y;
    const int n0  = blockIdx.x * 128;
    const int tid = threadIdx.x, lane = tid & 31, wid = tid >> 5;
    const int qb  = wid * 16;            // this warp's query-row base
    const int lr  = lane >> 2;           // 0..7
    const int lc  = lane & 3;            // 0..3

    // Load Q [32 d][128 n] and full K [32 d][1024 m] (raw fp32 bits)
    for (int e = tid; e < 32 * 128; e += 256) {
        int d = e >> 7, n = e & 127;
        sQ[d * 136 + n] = __float_as_uint(g_qkv[((size_t)b * OC + d) * HWSZ + n0 + n]);
    }
    for (int e = tid; e < 32 * 1024; e += 256) {
        int d = e >> 10, m = e & 1023;
        sK[d * 1032 + m] = __float_as_uint(g_k[((size_t)b * DQ + d) * MM + m]);
    }
    __syncthreads();

    // Preload Q A-fragments (constant across all key tiles): 4 k8-steps
    uint32_t qa[4][4];
#pragma unroll
    for (int ks = 0; ks < 4; ks++) {
        int d = ks * 8 + lc;
        qa[ks][0] = sQ[d * 136 + qb + lr];
        qa[ks][1] = sQ[d * 136 + qb + lr + 8];
        qa[ks][2] = sQ[(d + 4) * 136 + qb + lr];
        qa[ks][3] = sQ[(d + 4) * 136 + qb + lr + 8];
    }

    float oacc[16][4];
#pragma unroll
    for (int nf = 0; nf < 16; nf++)
#pragma unroll
        for (int j = 0; j < 4; j++) oacc[nf][j] = 0.0f;
    float rs0 = 0.0f, rs1 = 0.0f;

    for (int mt = 0; mt < 16; mt++) {
        const int mb = mt * 64;
        // Issue V-tile cp.async (sV not read until PV below; prev PV readers
        // finished before the trailing __syncthreads of the last iteration,
        // which for mt=0 is the post-load __syncthreads above).
#pragma unroll
        for (int it = 0; it < 8; it++) {            // 2048 float4
            int u = tid + it * 256;
            int d = u >> 4, mv = u & 15;
            cp16(&sV[d * 68 + mv * 4], g_v + ((size_t)b * DV + d) * MM + mb + mv * 4);
        }
        CP_COMMIT();

        // S = Q @ K_tile^T : per warp 16 q x 64 m  (overlaps V load)
        float sf[8][4];
#pragma unroll
        for (int nf = 0; nf < 8; nf++)
#pragma unroll
            for (int j = 0; j < 4; j++) sf[nf][j] = 0.0f;
#pragma unroll
        for (int ks = 0; ks < 4; ks++) {
            const int dr0 = (ks * 8 + lc) * 1032;
            const int dr1 = (ks * 8 + 4 + lc) * 1032;
#pragma unroll
            for (int nf = 0; nf < 8; nf++) {
                int mcol = mb + nf * 8 + lr;
                uint32_t bf[2] = { sK[dr0 + mcol], sK[dr1 + mcol] };
                mma_tf32(sf[nf], qa[ks], bf);
            }
        }
        // exp + rowsum; store E (raw fp32 bits)
#pragma unroll
        for (int nf = 0; nf < 8; nf++) {
            float e0 = __expf(sf[nf][0]);
            float e1 = __expf(sf[nf][1]);
            float e2 = __expf(sf[nf][2]);
            float e3 = __expf(sf[nf][3]);
            rs0 += e0 + e1;
            rs1 += e2 + e3;
            int col = nf * 8 + 2 * lc;
            uint32_t* p0 = &sE[(qb + lr) * 68 + col];
            uint32_t* p1 = &sE[(qb + lr + 8) * 68 + col];
            p0[0] = __float_as_uint(e0); p0[1] = __float_as_uint(e1);
            p1[0] = __float_as_uint(e2); p1[1] = __float_as_uint(e3);
        }
        CP_WAIT0();        // V tile arrived
        __syncthreads();   // sV visible + sE complete for all warps
        // O += E @ V^T : per warp 16 q x 128 d, k = 64 m (8 k8-steps)
#pragma unroll
        for (int ks = 0; ks < 8; ks++) {
            uint32_t ea[4];
            int m = ks * 8 + lc;
            ea[0] = sE[(qb + lr) * 68 + m];
            ea[1] = sE[(qb + lr + 8) * 68 + m];
            ea[2] = sE[(qb + lr) * 68 + m + 4];
            ea[3] = sE[(qb + lr + 8) * 68 + m + 4];
#pragma unroll
            for (int nf = 0; nf < 16; nf++) {
                int drow = (nf * 8 + lr) * 68;
                uint32_t bf[2] = { sV[drow + m], sV[drow + m + 4] };
                mma_tf32(oacc[nf], ea, bf);
            }
        }
        __syncthreads();   // PV done: sV/sE reusable next iteration
    }

    // Row-sum reduction across the 4 column-owner lanes (quad butterfly)
    rs0 += __shfl_xor_sync(0xffffffffu, rs0, 1);
    rs0 += __shfl_xor_sync(0xffffffffu, rs0, 2);
    rs1 += __shfl_xor_sync(0xffffffffu, rs1, 1);
    rs1 += __shfl_xor_sync(0xffffffffu, rs1, 2);
    const float inv0 = 1.0f / rs0, inv1 = 1.0f / rs1;

    // Normalize + stage O[q][d] (reuse sK region, stride 133: conflict-free).
    // Stride 133 is ODD -> scalar 4-byte stores only (float2 traps: misaligned).
    float* Os = (float*)dynsm;
#pragma unroll
    for (int nf = 0; nf < 16; nf++) {
        int col = nf * 8 + 2 * lc;
        float* q0 = &Os[(qb + lr) * 133 + col];
        float* q1 = &Os[(qb + lr + 8) * 133 + col];
        q0[0] = oacc[nf][0] * inv0;
        q0[1] = oacc[nf][1] * inv0;
        q1[0] = oacc[nf][2] * inv1;
        q1[1] = oacc[nf][3] * inv1;
    }
    __syncthreads();
    for (int e = tid; e < DV * 128; e += 256) {
        int d = e >> 7, q = e & 127;
        g_ao[((size_t)b * DV + d) * HWSZ + n0 + q] = Os[q * 133 + d];
    }
}

// ============================================================
// K4: out = imgs + scale * (w_out @ attn_out)  M=256(c) N=4096 K=128(d)
// Same double-buffered cp.async scheme as K1, 4 k-chunks.
// ============================================================
__global__ void __launch_bounds__(256) k_out_mma(const float* __restrict__ imgs,
                                                 const float* __restrict__ wout,
                                                 const float* __restrict__ scale_p,
                                                 float* __restrict__ out) {
    const int b  = blockIdx.z;
    const int c0 = blockIdx.y * 64;
    const int n0 = blockIdx.x * 256;
    const int tid = threadIdx.x, lane = tid & 31, wid = tid >> 5;
    const int wm = (wid >> 2) * 32;
    const int wn = (wid & 3) * 64;

    auto prefetch = [&](int ibuf, int kc) {
        uint32_t* sA = dynsm + G_SA(ibuf);
        uint32_t* sB = dynsm + G_SB(ibuf);
#pragma unroll
        for (int it = 0; it < 2; it++) {            // A: 64x32
            int u = tid + it * 256;
            int o = u >> 3, cv = u & 7;
            cp16(&sA[o * 36 + cv * 4], wout + (size_t)(c0 + o) * DV + kc + cv * 4);
        }
#pragma unroll
        for (int it = 0; it < 8; it++) {            // B: 32x256
            int u = tid + it * 256;
            int c = u >> 6, nv = u & 63;
            cp16(&sB[c * 264 + nv * 4],
                 g_ao + ((size_t)b * DV + kc + c) * HWSZ + n0 + nv * 4);
        }
        CP_COMMIT();
    };

    float acc[2][8][4];
#pragma unroll
    for (int mf = 0; mf < 2; mf++)
#pragma unroll
        for (int nf = 0; nf < 8; nf++)
#pragma unroll
            for (int j = 0; j < 4; j++) acc[mf][nf][j] = 0.0f;

    prefetch(0, 0);
    for (int ic = 0; ic < 4; ic++) {
        if (ic + 1 < 4) { prefetch((ic + 1) & 1, (ic + 1) * 32); CP_WAIT1(); }
        else            { CP_WAIT0(); }
        __syncthreads();
        const uint32_t* sA = dynsm + G_SA(ic & 1);
        const uint32_t* sB = dynsm + G_SB(ic & 1);
#pragma unroll
        for (int k8 = 0; k8 < 32; k8 += 8) {
            uint32_t a[2][4];
            const int ar = wm + (lane >> 2);
            const int ac = k8 + (lane & 3);
#pragma unroll
            for (int mf = 0; mf < 2; mf++) {
                int r = ar + mf * 16;
                a[mf][0] = sA[r * 36 + ac];
                a[mf][1] = sA[(r + 8) * 36 + ac];
                a[mf][2] = sA[r * 36 + ac + 4];
                a[mf][3] = sA[(r + 8) * 36 + ac + 4];
            }
#pragma unroll
            for (int nf = 0; nf < 8; nf++) {
                int bn = wn + nf * 8 + (lane >> 2);
                uint32_t bf[2];
                bf[0] = sB[(k8 + (lane & 3)) * 264 + bn];
                bf[1] = sB[(k8 + 4 + (lane & 3)) * 264 + bn];
                mma_tf32(acc[0][nf], a[0], bf);
                mma_tf32(acc[1][nf], a[1], bf);
            }
        }
        __syncthreads();
    }

    const float s = *scale_p;
#pragma unroll
    for (int mf = 0; mf < 2; mf++)
#pragma unroll
        for (int nf = 0; nf < 8; nf++) {
            int row = c0 + wm + mf * 16 + (lane >> 2);
            int col = wn + nf * 8 + 2 * (lane & 3);
            size_t i0 = ((size_t)b * CC + row) * HWSZ + n0 + col;
            size_t i1 = ((size_t)b * CC + row + 8) * HWSZ + n0 + col;
            float2 m0 = *(const float2*)&imgs[i0];
            float2 m1 = *(const float2*)&imgs[i1];
            *(float2*)&out[i0] = make_float2(m0.x + s * acc[mf][nf][0],
                                             m0.y + s * acc[mf][nf][1]);
            *(float2*)&out[i1] = make_float2(m1.x + s * acc[mf][nf][2],
                                             m1.y + s * acc[mf][nf][3]);
        }
}

// ============================================================
extern "C" void kernel_launch(void* const* d_in, const int* in_sizes, int n_in,
                              void* d_out, int out_size) {
    const float* imgs  = (const float*)d_in[0];
    const float* wqkv  = (const float*)d_in[1];
    const float* wout  = (const float*)d_in[2];
    const float* scale = (const float*)d_in[3];
    float* out = (float*)d_out;

    cudaFuncSetAttribute(k_qkv_mma,  cudaFuncAttributeMaxDynamicSharedMemorySize, GEMM_SMEM_BYTES);
    cudaFuncSetAttribute(k_attn_mma, cudaFuncAttributeMaxDynamicSharedMemorySize, SATT_SMEM_BYTES);
    cudaFuncSetAttribute(k_out_mma,  cudaFuncAttributeMaxDynamicSharedMemorySize, GEMM_SMEM_BYTES);

    k_qkv_mma<<<dim3(16, 3, 16), 256, GEMM_SMEM_BYTES>>>(imgs, wqkv);

    const int pool_total = BB * (DQ + DV) * MM;
    k_pool<<<(pool_total + 255) / 256, 256>>>();

    k_attn_mma<<<dim3(32, 16), 256, SATT_SMEM_BYTES>>>();

    k_out_mma<<<dim3(16, 4, 16), 256, GEMM_SMEM_BYTES>>>(imgs, wout, scale, out);
}

// round 12
// speedup vs baseline: 5.2060x; 1.3083x over previous
#include <cuda_runtime.h>
#include <cstdint>

// Problem constants
#define BB   16
#define CC   256
#define HH   64
#define WW   64
#define HWSZ 4096     // H*W
#define DQ   32       // C/8
#define DV   128      // C/2
#define OC   192      // 2*DQ + DV
#define MM   1024     // pooled spatial (32*32)

// Scratch (device globals: allocation-free rule)
// g_q : q channels only [b][d][hw]
// g_k : pooled K, layout [b][m][pd]  (pd = pair-permuted d within 8-groups)
// g_v : pooled V, layout [b][d][pm]  (pm = pair-permuted m within 8-groups)
// pair-perm within 8: j -> (j<4 ? 2j : 2(j-4)+1), i.e. order {0,4,1,5,2,6,3,7}
__device__ float g_q[BB * DQ * HWSZ];
__device__ float g_k[BB * MM * DQ];
__device__ float g_v[BB * DV * MM];
__device__ float g_ao[BB * DV * HWSZ];    // attention output [b][d][n]

// ---- tf32 mma.sync with RAW fp32 bits (HMMA reads tf32 subset; truncation) ----
__device__ __forceinline__ void mma_tf32(float* c, const uint32_t* a, const uint32_t* b) {
    asm volatile("mma.sync.aligned.m16n8k8.row.col.f32.tf32.tf32.f32 "
        "{%0,%1,%2,%3}, {%4,%5,%6,%7}, {%8,%9}, {%0,%1,%2,%3};"
        : "+f"(c[0]), "+f"(c[1]), "+f"(c[2]), "+f"(c[3])
        : "r"(a[0]), "r"(a[1]), "r"(a[2]), "r"(a[3]), "r"(b[0]), "r"(b[1]));
}

// ---- cp.async helpers ----
__device__ __forceinline__ void cp16(void* dst, const void* src) {
    uint32_t d = (uint32_t)__cvta_generic_to_shared(dst);
    asm volatile("cp.async.cg.shared.global [%0], [%1], 16;" :: "r"(d), "l"(src) : "memory");
}
#define CP_COMMIT() asm volatile("cp.async.commit_group;" ::: "memory")
#define CP_WAIT0()  asm volatile("cp.async.wait_group 0;" ::: "memory")
#define CP_WAIT1()  asm volatile("cp.async.wait_group 1;" ::: "memory")

extern __shared__ uint32_t dynsm[];

// ============================================================
// K1: qkv GEMM + fused 2x2 maxpool epilogue.
// per batch: M=192(o) N=4096(hw) K=256(c); CTA tile 64 x 256 (8 warps 2m x 4n).
// A 256-hw tile = 4 full image rows -> pooling is CTA-local.
//   by=0: rows 0-31 = q -> g_q direct; rows 32-63 = k channels -> pool -> g_k
//   by=1: v channels 0-63  -> pool -> g_v
//   by=2: v channels 64-127-> pool -> g_v
// ============================================================
#define G_SA(i) ((i) * 2304)              // 64*36
#define G_SB(i) (4608 + (i) * 8448)       // 32*264
#define GEMM_SMEM_BYTES ((4608 + 2 * 8448) * 4)   // 86016

__global__ void __launch_bounds__(256) k_qkv_mma(const float* __restrict__ imgs,
                                                 const float* __restrict__ wq) {
    const int b  = blockIdx.z;
    const int o0 = blockIdx.y * 64;
    const int n0 = blockIdx.x * 256;
    const int tid = threadIdx.x, lane = tid & 31, wid = tid >> 5;
    const int lr = lane >> 2, lc = lane & 3;
    const int wm = (wid >> 2) * 32;       // warp row base (0/32)
    const int wn = (wid & 3) * 64;        // warp col base
    const float* X = imgs + (size_t)b * CC * HWSZ;

    auto prefetch = [&](int ibuf, int kc) {
        uint32_t* sA = dynsm + G_SA(ibuf);
        uint32_t* sB = dynsm + G_SB(ibuf);
#pragma unroll
        for (int it = 0; it < 2; it++) {            // A: 64x32
            int u = tid + it * 256;
            int o = u >> 3, cv = u & 7;
            cp16(&sA[o * 36 + cv * 4], wq + (size_t)(o0 + o) * CC + kc + cv * 4);
        }
#pragma unroll
        for (int it = 0; it < 8; it++) {            // B: 32x256
            int u = tid + it * 256;
            int c = u >> 6, nv = u & 63;
            cp16(&sB[c * 264 + nv * 4], X + (size_t)(kc + c) * HWSZ + n0 + nv * 4);
        }
        CP_COMMIT();
    };

    float acc[2][8][4];
#pragma unroll
    for (int mf = 0; mf < 2; mf++)
#pragma unroll
        for (int nf = 0; nf < 8; nf++)
#pragma unroll
            for (int j = 0; j < 4; j++) acc[mf][nf][j] = 0.0f;

    prefetch(0, 0);
    for (int ic = 0; ic < 8; ic++) {
        if (ic + 1 < 8) { prefetch((ic + 1) & 1, (ic + 1) * 32); CP_WAIT1(); }
        else            { CP_WAIT0(); }
        __syncthreads();
        const uint32_t* sA = dynsm + G_SA(ic & 1);
        const uint32_t* sB = dynsm + G_SB(ic & 1);
#pragma unroll
        for (int k8 = 0; k8 < 32; k8 += 8) {
            uint32_t a[2][4];
            const int ar = wm + lr;
            const int ac = k8 + lc;
#pragma unroll
            for (int mf = 0; mf < 2; mf++) {
                int r = ar + mf * 16;
                a[mf][0] = sA[r * 36 + ac];
                a[mf][1] = sA[(r + 8) * 36 + ac];
                a[mf][2] = sA[r * 36 + ac + 4];
                a[mf][3] = sA[(r + 8) * 36 + ac + 4];
            }
#pragma unroll
            for (int nf = 0; nf < 8; nf++) {
                int bn = wn + nf * 8 + lr;
                uint32_t bf[2];
                bf[0] = sB[(k8 + lc) * 264 + bn];
                bf[1] = sB[(k8 + 4 + lc) * 264 + bn];
                mma_tf32(acc[0][nf], a[0], bf);
                mma_tf32(acc[1][nf], a[1], bf);
            }
        }
        __syncthreads();
    }

    // -------- fused epilogue: q direct store + pool k/v --------
    float* stg = (float*)dynsm;                 // [rows][260], <= 66.5 KB
    const int bxm = blockIdx.x * 64;            // this CTA's pooled-m base

    if (o0 == 0) {
        if (wm == 0) {
            // warps 0-3: q rows 0..31 -> g_q
#pragma unroll
            for (int mf = 0; mf < 2; mf++)
#pragma unroll
                for (int nf = 0; nf < 8; nf++) {
                    int row = mf * 16 + lr;
                    int col = wn + nf * 8 + 2 * lc;
                    float* o = g_q + ((size_t)b * DQ + row) * HWSZ + n0 + col;
                    *(float2*)o = make_float2(acc[0 + 0][nf][0], acc[0][nf][1]);
                    // careful: mf indexes acc
                    *(float2*)(o) = make_float2(acc[mf][nf][0], acc[mf][nf][1]);
                    *(float2*)(g_q + ((size_t)b * DQ + row + 8) * HWSZ + n0 + col) =
                        make_float2(acc[mf][nf][2], acc[mf][nf][3]);
                }
        } else {
            // warps 4-7: stage k rows (qkv rows 32..63 -> staged 0..31)
#pragma unroll
            for (int mf = 0; mf < 2; mf++)
#pragma unroll
                for (int nf = 0; nf < 8; nf++) {
                    int r   = mf * 16 + lr;
                    int col = wn + nf * 8 + 2 * lc;
                    *(float2*)&stg[r * 260 + col] =
                        make_float2(acc[mf][nf][0], acc[mf][nf][1]);
                    *(float2*)&stg[(r + 8) * 260 + col] =
                        make_float2(acc[mf][nf][2], acc[mf][nf][3]);
                }
        }
        __syncthreads();
        // pool K -> g_k[b][m][pd] (d pair-permuted); writes fully coalesced
        for (int e = tid; e < 32 * 64; e += 256) {
            int pd = e & 31, mloc = e >> 5;
            int p8 = pd & 7;
            int ch = (pd & ~7) + ((p8 & 1) ? (p8 >> 1) + 4 : (p8 >> 1));
            int myl = mloc >> 5, mx = mloc & 31;
            const float* s0 = stg + ch * 260 + myl * 128 + 2 * mx;
            float v = fmaxf(fmaxf(s0[0], s0[1]), fmaxf(s0[64], s0[65]));
            g_k[((size_t)b * MM + bxm + mloc) * DQ + pd] = v;
        }
    } else {
        const int chb = o0 - 64;     // v channel base (0 or 64)
#pragma unroll
        for (int mf = 0; mf < 2; mf++)
#pragma unroll
            for (int nf = 0; nf < 8; nf++) {
                int r   = wm + mf * 16 + lr;
                int col = wn + nf * 8 + 2 * lc;
                *(float2*)&stg[r * 260 + col] =
                    make_float2(acc[mf][nf][0], acc[mf][nf][1]);
                *(float2*)&stg[(r + 8) * 260 + col] =
                    make_float2(acc[mf][nf][2], acc[mf][nf][3]);
            }
        __syncthreads();
        // pool V -> g_v[b][d][pm] (m pair-permuted within 8-groups)
        for (int e = tid; e < 64 * 64; e += 256) {
            int pml = e & 63, ch = e >> 6;
            int p8 = pml & 7;
            int mloc = (pml & ~7) + ((p8 & 1) ? (p8 >> 1) + 4 : (p8 >> 1));
            int myl = mloc >> 5, mx = mloc & 31;
            const float* s0 = stg + ch * 260 + myl * 128 + 2 * mx;
            float v = fmaxf(fmaxf(s0[0], s0[1]), fmaxf(s0[64], s0[65]));
            g_v[((size_t)b * DV + chb + ch) * MM + bxm + pml] = v;
        }
    }
}

// ============================================================
// K3: flash attention, tf32 mma, streamed K tiles, 2 CTAs/SM.
// CTA: 256 thr = 8 warps x 16 q rows, 128-query tile. grid (32, 16).
// SMEM (words): sQ[32][136] | sK2 2x[64 m][40 pd] | sV[128 d][72 pm] | sE[128 q][72 pm]
// All mma fragment LDS are float2, bank-conflict-free (8*lr+2*lc patterns).
// ============================================================
#define AT_Q 0
#define AT_K 4352                    // + ibuf*2560
#define AT_V 9472
#define AT_E 18688
#define SATT_SMEM_BYTES ((18688 + 9216) * 4)     // 111616

__global__ void __launch_bounds__(256, 2) k_attn_mma() {
    uint32_t* sQ = dynsm + AT_Q;
    uint32_t* sV = dynsm + AT_V;
    uint32_t* sE = dynsm + AT_E;

    const int b   = blockIdx.y;
    const int n0  = blockIdx.x * 128;
    const int tid = threadIdx.x, lane = tid & 31, wid = tid >> 5;
    const int qb  = wid * 16;
    const int lr  = lane >> 2;
    const int lc  = lane & 3;
    // permuted E-store positions for c-frag cols j0=2lc, j1=2lc+1
    const int pos0 = (lc < 2) ? 4 * lc : 4 * lc - 7;
    const int pos1 = (lc < 2) ? 4 * lc + 2 : 4 * lc - 5;

    // prologue: async-load Q [32][128] and K tile 0
#pragma unroll
    for (int it = 0; it < 4; it++) {             // Q: 1024 cp16
        int u = tid + it * 256;
        int d = u >> 5, nv = u & 31;
        cp16(&sQ[d * 136 + nv * 4], g_q + ((size_t)b * DQ + d) * HWSZ + n0 + nv * 4);
    }
#pragma unroll
    for (int it = 0; it < 2; it++) {             // K0: 512 cp16
        int u = tid + it * 256;
        int ml = u >> 3, c = u & 7;
        cp16(&dynsm[AT_K + ml * 40 + c * 4],
             g_k + ((size_t)b * MM + ml) * DQ + c * 4);
    }
    CP_COMMIT();
    CP_WAIT0();
    __syncthreads();

    // preload Q A-fragments
    uint32_t qa[4][4];
#pragma unroll
    for (int ks = 0; ks < 4; ks++) {
        int d = ks * 8 + lc;
        qa[ks][0] = sQ[d * 136 + qb + lr];
        qa[ks][1] = sQ[d * 136 + qb + lr + 8];
        qa[ks][2] = sQ[(d + 4) * 136 + qb + lr];
        qa[ks][3] = sQ[(d + 4) * 136 + qb + lr + 8];
    }

    float oacc[16][4];
#pragma unroll
    for (int nf = 0; nf < 16; nf++)
#pragma unroll
        for (int j = 0; j < 4; j++) oacc[nf][j] = 0.0f;
    float rs0 = 0.0f, rs1 = 0.0f;

    for (int mt = 0; mt < 16; mt++) {
        const int mb = mt * 64;
        // prefetch next K tile (used next iter; drained at this iter's mid-wait)
        if (mt + 1 < 16) {
#pragma unroll
            for (int it = 0; it < 2; it++) {
                int u = tid + it * 256;
                int ml = u >> 3, c = u & 7;
                cp16(&dynsm[AT_K + ((mt + 1) & 1) * 2560 + ml * 40 + c * 4],
                     g_k + ((size_t)b * MM + mb + 64 + ml) * DQ + c * 4);
            }
            CP_COMMIT();
        }
        // V tile for this iter (pair-permuted m in gmem -> contiguous)
#pragma unroll
        for (int it = 0; it < 8; it++) {
            int u = tid + it * 256;
            int d = u >> 4, mv = u & 15;
            cp16(&sV[d * 72 + mv * 4], g_v + ((size_t)b * DV + d) * MM + mb + mv * 4);
        }
        CP_COMMIT();

        // S = Q @ K_tile^T (K(mt) visible via prev iter's mid sync / prologue)
        const uint32_t* sK2 = dynsm + AT_K + (mt & 1) * 2560;
#pragma unroll
        for (int half = 0; half < 2; half++) {
            float sf[4][4];
#pragma unroll
            for (int f = 0; f < 4; f++)
#pragma unroll
                for (int j = 0; j < 4; j++) sf[f][j] = 0.0f;
#pragma unroll
            for (int ks = 0; ks < 4; ks++) {
#pragma unroll
                for (int f = 0; f < 4; f++) {
                    int nf = half * 4 + f;
                    const uint32_t* bp = &sK2[(nf * 8 + lr) * 40 + ks * 8 + 2 * lc];
                    mma_tf32(sf[f], qa[ks], bp);   // float2-equivalent pair (b0,b1)
                }
            }
#pragma unroll
            for (int f = 0; f < 4; f++) {
                int nf = half * 4 + f;
                float e0 = __expf(sf[f][0]);
                float e1 = __expf(sf[f][1]);
                float e2 = __expf(sf[f][2]);
                float e3 = __expf(sf[f][3]);
                rs0 += e0 + e1;
                rs1 += e2 + e3;
                uint32_t* p0 = &sE[(qb + lr) * 72 + nf * 8];
                uint32_t* p1 = &sE[(qb + lr + 8) * 72 + nf * 8];
                p0[pos0] = __float_as_uint(e0); p0[pos1] = __float_as_uint(e1);
                p1[pos0] = __float_as_uint(e2); p1[pos1] = __float_as_uint(e3);
            }
        }

        CP_WAIT0();        // V(mt) (and K(mt+1)) arrived
        __syncthreads();   // sV + sE visible to all warps
        // O += E @ V^T : 8 k-steps x 16 d-frags, all fragment loads = LDS.64
#pragma unroll
        for (int ks = 0; ks < 8; ks++) {
            uint32_t ea[4];
            {
                const uint32_t* a0 = &sE[(qb + lr) * 72 + ks * 8 + 2 * lc];
                const uint32_t* a1 = &sE[(qb + lr + 8) * 72 + ks * 8 + 2 * lc];
                ea[0] = a0[0]; ea[2] = a0[1];
                ea[1] = a1[0]; ea[3] = a1[1];
            }
#pragma unroll
            for (int nf = 0; nf < 16; nf++) {
                const uint32_t* bp = &sV[(nf * 8 + lr) * 72 + ks * 8 + 2 * lc];
                mma_tf32(oacc[nf], ea, bp);
            }
        }
        __syncthreads();   // PV done: sV/sE/sK2(other buf) reusable
    }

    // rowsum reduce across quad lanes
    rs0 += __shfl_xor_sync(0xffffffffu, rs0, 1);
    rs0 += __shfl_xor_sync(0xffffffffu, rs0, 2);
    rs1 += __shfl_xor_sync(0xffffffffu, rs1, 1);
    rs1 += __shfl_xor_sync(0xffffffffu, rs1, 2);
    const float inv0 = 1.0f / rs0, inv1 = 1.0f / rs1;

    // Normalize + stage O[q][d] at stride 133 (odd -> scalar stores only)
    float* Os = (float*)(dynsm + AT_V);
#pragma unroll
    for (int nf = 0; nf < 16; nf++) {
        int col = nf * 8 + 2 * lc;
        float* q0 = &Os[(qb + lr) * 133 + col];
        float* q1 = &Os[(qb + lr + 8) * 133 + col];
        q0[0] = oacc[nf][0] * inv0;
        q0[1] = oacc[nf][1] * inv0;
        q1[0] = oacc[nf][2] * inv1;
        q1[1] = oacc[nf][3] * inv1;
    }
    __syncthreads();
    for (int e = tid; e < DV * 128; e += 256) {
        int d = e >> 7, q = e & 127;
        g_ao[((size_t)b * DV + d) * HWSZ + n0 + q] = Os[q * 133 + d];
    }
}

// ============================================================
// K4: out = imgs + scale * (w_out @ attn_out)  M=256(c) N=4096 K=128(d)
// ============================================================
__global__ void __launch_bounds__(256) k_out_mma(const float* __restrict__ imgs,
                                                 const float* __restrict__ wout,
                                                 const float* __restrict__ scale_p,
                                                 float* __restrict__ out) {
    const int b  = blockIdx.z;
    const int c0 = blockIdx.y * 64;
    const int n0 = blockIdx.x * 256;
    const int tid = threadIdx.x, lane = tid & 31, wid = tid >> 5;
    const int lr = lane >> 2, lc = lane & 3;
    const int wm = (wid >> 2) * 32;
    const int wn = (wid & 3) * 64;

    auto prefetch = [&](int ibuf, int kc) {
        uint32_t* sA = dynsm + G_SA(ibuf);
        uint32_t* sB = dynsm + G_SB(ibuf);
#pragma unroll
        for (int it = 0; it < 2; it++) {
            int u = tid + it * 256;
            int o = u >> 3, cv = u & 7;
            cp16(&sA[o * 36 + cv * 4], wout + (size_t)(c0 + o) * DV + kc + cv * 4);
        }
#pragma unroll
        for (int it = 0; it < 8; it++) {
            int u = tid + it * 256;
            int c = u >> 6, nv = u & 63;
            cp16(&sB[c * 264 + nv * 4],
                 g_ao + ((size_t)b * DV + kc + c) * HWSZ + n0 + nv * 4);
        }
        CP_COMMIT();
    };

    float acc[2][8][4];
#pragma unroll
    for (int mf = 0; mf < 2; mf++)
#pragma unroll
        for (int nf = 0; nf < 8; nf++)
#pragma unroll
            for (int j = 0; j < 4; j++) acc[mf][nf][j] = 0.0f;

    prefetch(0, 0);
    for (int ic = 0; ic < 4; ic++) {
        if (ic + 1 < 4) { prefetch((ic + 1) & 1, (ic + 1) * 32); CP_WAIT1(); }
        else            { CP_WAIT0(); }
        __syncthreads();
        const uint32_t* sA = dynsm + G_SA(ic & 1);
        const uint32_t* sB = dynsm + G_SB(ic & 1);
#pragma unroll
        for (int k8 = 0; k8 < 32; k8 += 8) {
            uint32_t a[2][4];
            const int ar = wm + lr;
            const int ac = k8 + lc;
#pragma unroll
            for (int mf = 0; mf < 2; mf++) {
                int r = ar + mf * 16;
                a[mf][0] = sA[r * 36 + ac];
                a[mf][1] = sA[(r + 8) * 36 + ac];
                a[mf][2] = sA[r * 36 + ac + 4];
                a[mf][3] = sA[(r + 8) * 36 + ac + 4];
            }
#pragma unroll
            for (int nf = 0; nf < 8; nf++) {
                int bn = wn + nf * 8 + lr;
                uint32_t bf[2];
                bf[0] = sB[(k8 + lc) * 264 + bn];
                bf[1] = sB[(k8 + 4 + lc) * 264 + bn];
                mma_tf32(acc[0][nf], a[0], bf);
                mma_tf32(acc[1][nf], a[1], bf);
            }
        }
        __syncthreads();
    }

    const float s = *scale_p;
#pragma unroll
    for (int mf = 0; mf < 2; mf++)
#pragma unroll
        for (int nf = 0; nf < 8; nf++) {
            int row = c0 + wm + mf * 16 + lr;
            int col = wn + nf * 8 + 2 * lc;
            size_t i0 = ((size_t)b * CC + row) * HWSZ + n0 + col;
            size_t i1 = ((size_t)b * CC + row + 8) * HWSZ + n0 + col;
            float2 m0 = *(const float2*)&imgs[i0];
            float2 m1 = *(const float2*)&imgs[i1];
            *(float2*)&out[i0] = make_float2(m0.x + s * acc[mf][nf][0],
                                             m0.y + s * acc[mf][nf][1]);
            *(float2*)&out[i1] = make_float2(m1.x + s * acc[mf][nf][2],
                                             m1.y + s * acc[mf][nf][3]);
        }
}

// ============================================================
extern "C" void kernel_launch(void* const* d_in, const int* in_sizes, int n_in,
                              void* d_out, int out_size) {
    const float* imgs  = (const float*)d_in[0];
    const float* wqkv  = (const float*)d_in[1];
    const float* wout  = (const float*)d_in[2];
    const float* scale = (const float*)d_in[3];
    float* out = (float*)d_out;

    cudaFuncSetAttribute(k_qkv_mma,  cudaFuncAttributeMaxDynamicSharedMemorySize, GEMM_SMEM_BYTES);
    cudaFuncSetAttribute(k_attn_mma, cudaFuncAttributeMaxDynamicSharedMemorySize, SATT_SMEM_BYTES);
    cudaFuncSetAttribute(k_out_mma,  cudaFuncAttributeMaxDynamicSharedMemorySize, GEMM_SMEM_BYTES);

    k_qkv_mma<<<dim3(16, 3, 16), 256, GEMM_SMEM_BYTES>>>(imgs, wqkv);

    k_attn_mma<<<dim3(32, 16), 256, SATT_SMEM_BYTES>>>();

    k_out_mma<<<dim3(16, 4, 16), 256, GEMM_SMEM_BYTES>>>(imgs, wout, scale, out);
}

// round 14
// speedup vs baseline: 6.3911x; 1.2276x over previous
#include <cuda_runtime.h>
#include <cstdint>

// Problem constants
#define BB   16
#define CC   256
#define HH   64
#define WW   64
#define HWSZ 4096     // H*W
#define DQ   32       // C/8
#define DV   128      // C/2
#define OC   192      // 2*DQ + DV
#define MM   1024     // pooled spatial (32*32)

// Scratch (device globals)
// g_q  : q channels fp32 [b][d][hw]
// g_k  : pooled K fp32 [b][m][pd]      (pd = pair-permuted d within 8-groups)
// g_v2 : pooled V fp16x2 [b][d][u]     (u = half2 unit = m/2, slot-permuted within 8-unit groups)
// g_ao2: attn out fp16x2 [b][n][du]    (du = half2 unit = d/2, slot-permuted within 8-unit groups)
// slot-perm within 8: slot s holds unit {0,4,1,5,2,6,3,7}[s];  unit p -> slot = (p<4)? 2p : 2(p-4)+1
__device__ float    g_q  [BB * DQ * HWSZ];
__device__ float    g_k  [BB * MM * DQ];
__device__ uint32_t g_v2 [BB * DV * (MM / 2)];
__device__ uint32_t g_ao2[BB * HWSZ * (DV / 2)];

// ---- mma helpers (baseline ISA) ----
// tf32, raw fp32 bits in operands (HMMA reads tf32 subset)
__device__ __forceinline__ void mma_tf32(float* c, const uint32_t* a, const uint32_t* b) {
    asm volatile("mma.sync.aligned.m16n8k8.row.col.f32.tf32.tf32.f32 "
        "{%0,%1,%2,%3}, {%4,%5,%6,%7}, {%8,%9}, {%0,%1,%2,%3};"
        : "+f"(c[0]), "+f"(c[1]), "+f"(c[2]), "+f"(c[3])
        : "r"(a[0]), "r"(a[1]), "r"(a[2]), "r"(a[3]), "r"(b[0]), "r"(b[1]));
}
// fp16 in, fp32 accum
__device__ __forceinline__ void mma_f16(float* c, uint32_t a0, uint32_t a1, uint32_t a2,
                                        uint32_t a3, uint32_t b0, uint32_t b1) {
    asm volatile("mma.sync.aligned.m16n8k16.row.col.f32.f16.f16.f32 "
        "{%0,%1,%2,%3}, {%4,%5,%6,%7}, {%8,%9}, {%0,%1,%2,%3};"
        : "+f"(c[0]), "+f"(c[1]), "+f"(c[2]), "+f"(c[3])
        : "r"(a0), "r"(a1), "r"(a2), "r"(a3), "r"(b0), "r"(b1));
}
// pack half2: lo = first arg
__device__ __forceinline__ uint32_t pack_h2(float lo, float hi) {
    uint32_t r;
    asm("cvt.rn.f16x2.f32 %0, %1, %2;" : "=r"(r) : "f"(hi), "f"(lo));
    return r;
}

// ---- cp.async helpers ----
__device__ __forceinline__ void cp16(void* dst, const void* src) {
    uint32_t d = (uint32_t)__cvta_generic_to_shared(dst);
    asm volatile("cp.async.cg.shared.global [%0], [%1], 16;" :: "r"(d), "l"(src) : "memory");
}
#define CP_COMMIT() asm volatile("cp.async.commit_group;" ::: "memory")
#define CP_WAIT0()  asm volatile("cp.async.wait_group 0;" ::: "memory")
#define CP_WAIT1()  asm volatile("cp.async.wait_group 1;" ::: "memory")

extern __shared__ uint32_t dynsm[];

// ============================================================
// K1: qkv GEMM (tf32) + fused 2x2 maxpool epilogue.
// by=0: rows 0-31 q -> g_q; rows 32-63 k -> pool -> g_k (fp32, pd-perm)
// by=1/2: v chans -> pool -> g_v2 (fp16x2, unit-perm)
// ============================================================
#define G_SA(i) ((i) * 2304)              // 64*36
#define G_SB(i) (4608 + (i) * 8448)       // 32*264
#define GEMM_SMEM_BYTES ((4608 + 2 * 8448) * 4)   // 86016

__global__ void __launch_bounds__(256) k_qkv_mma(const float* __restrict__ imgs,
                                                 const float* __restrict__ wq) {
    const int b  = blockIdx.z;
    const int o0 = blockIdx.y * 64;
    const int n0 = blockIdx.x * 256;
    const int tid = threadIdx.x, lane = tid & 31, wid = tid >> 5;
    const int lr = lane >> 2, lc = lane & 3;
    const int wm = (wid >> 2) * 32;
    const int wn = (wid & 3) * 64;
    const float* X = imgs + (size_t)b * CC * HWSZ;

    auto prefetch = [&](int ibuf, int kc) {
        uint32_t* sA = dynsm + G_SA(ibuf);
        uint32_t* sB = dynsm + G_SB(ibuf);
#pragma unroll
        for (int it = 0; it < 2; it++) {
            int u = tid + it * 256;
            int o = u >> 3, cv = u & 7;
            cp16(&sA[o * 36 + cv * 4], wq + (size_t)(o0 + o) * CC + kc + cv * 4);
        }
#pragma unroll
        for (int it = 0; it < 8; it++) {
            int u = tid + it * 256;
            int c = u >> 6, nv = u & 63;
            cp16(&sB[c * 264 + nv * 4], X + (size_t)(kc + c) * HWSZ + n0 + nv * 4);
        }
        CP_COMMIT();
    };

    float acc[2][8][4];
#pragma unroll
    for (int mf = 0; mf < 2; mf++)
#pragma unroll
        for (int nf = 0; nf < 8; nf++)
#pragma unroll
            for (int j = 0; j < 4; j++) acc[mf][nf][j] = 0.0f;

    prefetch(0, 0);
    for (int ic = 0; ic < 8; ic++) {
        if (ic + 1 < 8) { prefetch((ic + 1) & 1, (ic + 1) * 32); CP_WAIT1(); }
        else            { CP_WAIT0(); }
        __syncthreads();
        const uint32_t* sA = dynsm + G_SA(ic & 1);
        const uint32_t* sB = dynsm + G_SB(ic & 1);
#pragma unroll
        for (int k8 = 0; k8 < 32; k8 += 8) {
            uint32_t a[2][4];
            const int ar = wm + lr;
            const int ac = k8 + lc;
#pragma unroll
            for (int mf = 0; mf < 2; mf++) {
                int r = ar + mf * 16;
                a[mf][0] = sA[r * 36 + ac];
                a[mf][1] = sA[(r + 8) * 36 + ac];
                a[mf][2] = sA[r * 36 + ac + 4];
                a[mf][3] = sA[(r + 8) * 36 + ac + 4];
            }
#pragma unroll
            for (int nf = 0; nf < 8; nf++) {
                int bn = wn + nf * 8 + lr;
                uint32_t bf[2];
                bf[0] = sB[(k8 + lc) * 264 + bn];
                bf[1] = sB[(k8 + 4 + lc) * 264 + bn];
                mma_tf32(acc[0][nf], a[0], bf);
                mma_tf32(acc[1][nf], a[1], bf);
            }
        }
        __syncthreads();
    }

    // -------- fused epilogue --------
    float* stg = (float*)dynsm;                 // [rows][260]
    const int bxm = blockIdx.x * 64;            // pooled-m base of this CTA

    if (o0 == 0) {
        if (wm == 0) {
            // warps 0-3: q rows 0..31 -> g_q
#pragma unroll
            for (int mf = 0; mf < 2; mf++)
#pragma unroll
                for (int nf = 0; nf < 8; nf++) {
                    int row = mf * 16 + lr;
                    int col = wn + nf * 8 + 2 * lc;
                    *(float2*)(g_q + ((size_t)b * DQ + row) * HWSZ + n0 + col) =
                        make_float2(acc[mf][nf][0], acc[mf][nf][1]);
                    *(float2*)(g_q + ((size_t)b * DQ + row + 8) * HWSZ + n0 + col) =
                        make_float2(acc[mf][nf][2], acc[mf][nf][3]);
                }
        } else {
            // warps 4-7: stage k rows (qkv rows 32..63 -> staged 0..31)
#pragma unroll
            for (int mf = 0; mf < 2; mf++)
#pragma unroll
                for (int nf = 0; nf < 8; nf++) {
                    int r   = mf * 16 + lr;
                    int col = wn + nf * 8 + 2 * lc;
                    *(float2*)&stg[r * 260 + col] =
                        make_float2(acc[mf][nf][0], acc[mf][nf][1]);
                    *(float2*)&stg[(r + 8) * 260 + col] =
                        make_float2(acc[mf][nf][2], acc[mf][nf][3]);
                }
        }
        __syncthreads();
        // pool K -> g_k[b][m][pd] fp32
        for (int e = tid; e < 32 * 64; e += 256) {
            int pd = e & 31, mloc = e >> 5;
            int p8 = pd & 7;
            int ch = (pd & ~7) + ((p8 & 1) ? (p8 >> 1) + 4 : (p8 >> 1));
            int myl = mloc >> 5, mx = mloc & 31;
            const float* s0 = stg + ch * 260 + myl * 128 + 2 * mx;
            float v = fmaxf(fmaxf(s0[0], s0[1]), fmaxf(s0[64], s0[65]));
            g_k[((size_t)b * MM + bxm + mloc) * DQ + pd] = v;
        }
    } else {
        const int chb = o0 - 64;     // v channel base (0 or 64)
#pragma unroll
        for (int mf = 0; mf < 2; mf++)
#pragma unroll
            for (int nf = 0; nf < 8; nf++) {
                int r   = wm + mf * 16 + lr;
                int col = wn + nf * 8 + 2 * lc;
                *(float2*)&stg[r * 260 + col] =
                    make_float2(acc[mf][nf][0], acc[mf][nf][1]);
                *(float2*)&stg[(r + 8) * 260 + col] =
                    make_float2(acc[mf][nf][2], acc[mf][nf][3]);
            }
        __syncthreads();
        // pool V -> g_v2[b][d][unit-slot] fp16x2, slot-permuted
        for (int e = tid; e < 64 * 32; e += 256) {
            int sl = e & 31, ch = e >> 5;
            int g = sl >> 3, p = sl & 7;
            int unit = g * 8 + ((p & 1) ? (p >> 1) + 4 : (p >> 1));
            float vv[2];
#pragma unroll
            for (int h = 0; h < 2; h++) {
                int mloc = 2 * unit + h;
                int myl = mloc >> 5, mx = mloc & 31;
                const float* s0 = stg + ch * 260 + myl * 128 + 2 * mx;
                vv[h] = fmaxf(fmaxf(s0[0], s0[1]), fmaxf(s0[64], s0[65]));
            }
            g_v2[((size_t)b * DV + chb + ch) * (MM / 2) + blockIdx.x * 32 + sl] =
                pack_h2(vv[0], vv[1]);
        }
    }
}

// ============================================================
// K3: flash attention. S in tf32, PV in fp16 (m16n8k16).
// CTA 256 thr = 8 warps x 16q, 128-query tile, grid (32,16), 2 CTA/SM.
// SMEM words: sQ[32][132] | sK 2x[64][40] | sV 2x[128][40] (h2) | sE[128][40] (h2)
// ============================================================
#define AQ 0
#define AK 4224
#define AV 9344
#define AE 19584
#define SATT_SMEM_BYTES ((AE + 5120) * 4)    // 98816

__global__ void __launch_bounds__(256, 2) k_attn_mma() {
    uint32_t* sQ = dynsm + AQ;
    uint32_t* sE = dynsm + AE;

    const int b   = blockIdx.y;
    const int n0  = blockIdx.x * 128;
    const int tid = threadIdx.x, lane = tid & 31, wid = tid >> 5;
    const int qb  = wid * 16;
    const int lr  = lane >> 2;
    const int lc  = lane & 3;

    // tile loaders
    auto load_k = [&](int mt) {
        uint32_t* dst = dynsm + AK + (mt & 1) * 2560;
#pragma unroll
        for (int it = 0; it < 2; it++) {
            int u = tid + it * 256;
            int ml = u >> 3, c = u & 7;
            cp16(&dst[ml * 40 + c * 4], g_k + ((size_t)b * MM + mt * 64 + ml) * DQ + c * 4);
        }
    };
    auto load_v = [&](int mt) {
        uint32_t* dst = dynsm + AV + (mt & 1) * 5120;
#pragma unroll
        for (int it = 0; it < 4; it++) {
            int u = tid + it * 256;
            int d = u >> 3, c = u & 7;
            cp16(&dst[d * 40 + c * 4],
                 g_v2 + ((size_t)b * DV + d) * (MM / 2) + mt * 32 + c * 4);
        }
    };

    // prologue: Q + K0 + V0
#pragma unroll
    for (int it = 0; it < 4; it++) {
        int u = tid + it * 256;
        int d = u >> 5, nv = u & 31;
        cp16(&sQ[d * 132 + nv * 4], g_q + ((size_t)b * DQ + d) * HWSZ + n0 + nv * 4);
    }
    load_k(0);
    load_v(0);
    CP_COMMIT();
    CP_WAIT0();
    __syncthreads();

    // preload Q A-fragments (tf32)
    uint32_t qa[4][4];
#pragma unroll
    for (int ks = 0; ks < 4; ks++) {
        int d = ks * 8 + lc;
        qa[ks][0] = sQ[d * 132 + qb + lr];
        qa[ks][1] = sQ[d * 132 + qb + lr + 8];
        qa[ks][2] = sQ[(d + 4) * 132 + qb + lr];
        qa[ks][3] = sQ[(d + 4) * 132 + qb + lr + 8];
    }

    float oacc[16][4];
#pragma unroll
    for (int nf = 0; nf < 16; nf++)
#pragma unroll
        for (int j = 0; j < 4; j++) oacc[nf][j] = 0.0f;
    float rs0 = 0.0f, rs1 = 0.0f;

    for (int mt = 0; mt < 16; mt++) {
        if (mt > 0) CP_WAIT0();   // drain K(mt),V(mt) prefetch
        __syncthreads();          // tiles visible; prev PV done (sE safe)

        // S = Q @ K_tile^T (tf32)
        const uint32_t* sK2 = dynsm + AK + (mt & 1) * 2560;
        float sf[8][4];
#pragma unroll
        for (int nf = 0; nf < 8; nf++)
#pragma unroll
            for (int j = 0; j < 4; j++) sf[nf][j] = 0.0f;
#pragma unroll
        for (int ks = 0; ks < 4; ks++) {
#pragma unroll
            for (int nf = 0; nf < 8; nf++) {
                const uint32_t* bp = &sK2[(nf * 8 + lr) * 40 + ks * 8 + 2 * lc];
                mma_tf32(sf[nf], qa[ks], bp);
            }
        }
        // exp + rowsum; store E as permuted half2
#pragma unroll
        for (int nf = 0; nf < 8; nf++) {
            float e0 = __expf(sf[nf][0]);
            float e1 = __expf(sf[nf][1]);
            float e2 = __expf(sf[nf][2]);
            float e3 = __expf(sf[nf][3]);
            rs0 += e0 + e1;
            rs1 += e2 + e3;
            int w = (nf >> 1) * 8 + 2 * lc + (nf & 1);   // slot of unit 4nf+lc
            sE[(qb + lr) * 40 + w]     = pack_h2(e0, e1);
            sE[(qb + lr + 8) * 40 + w] = pack_h2(e2, e3);
        }
        __syncthreads();          // sE complete

        // prefetch next tiles (overlaps PV; prev-buffer readers all past sync)
        if (mt + 1 < 16) {
            load_k(mt + 1);
            load_v(mt + 1);
            CP_COMMIT();
        }

        // O += E @ V (fp16, 4 k16-steps x 16 d-frags)
        const uint32_t* sVb = dynsm + AV + (mt & 1) * 5120;
#pragma unroll
        for (int ks = 0; ks < 4; ks++) {
            uint2 eL = *(const uint2*)&sE[(qb + lr) * 40 + ks * 8 + 2 * lc];
            uint2 eH = *(const uint2*)&sE[(qb + lr + 8) * 40 + ks * 8 + 2 * lc];
#pragma unroll
            for (int nf = 0; nf < 16; nf++) {
                uint2 bb = *(const uint2*)&sVb[(nf * 8 + lr) * 40 + ks * 8 + 2 * lc];
                mma_f16(oacc[nf], eL.x, eH.x, eL.y, eH.y, bb.x, bb.y);
            }
        }
    }

    // rowsum reduce across quad lanes
    rs0 += __shfl_xor_sync(0xffffffffu, rs0, 1);
    rs0 += __shfl_xor_sync(0xffffffffu, rs0, 2);
    rs1 += __shfl_xor_sync(0xffffffffu, rs1, 1);
    rs1 += __shfl_xor_sync(0xffffffffu, rs1, 2);
    const float inv0 = 1.0f / rs0, inv1 = 1.0f / rs1;

    // Normalize, pack half2 (d-pairs native in C-frag), stage permuted [q][72]
    uint32_t* Os = dynsm;   // 128*72 = 9216 words, overlays sQ/sK (done)
#pragma unroll
    for (int nf = 0; nf < 16; nf++) {
        int w = (nf >> 1) * 8 + 2 * lc + (nf & 1);   // slot of unit 4nf+lc (of 64)
        Os[(qb + lr) * 72 + w]     = pack_h2(oacc[nf][0] * inv0, oacc[nf][1] * inv0);
        Os[(qb + lr + 8) * 72 + w] = pack_h2(oacc[nf][2] * inv1, oacc[nf][3] * inv1);
    }
    __syncthreads();
    // coalesced write g_ao2[b][n][du]
    for (int e = tid; e < 128 * 64; e += 256) {
        int q = e >> 6, u = e & 63;
        g_ao2[((size_t)b * HWSZ + n0 + q) * 64 + u] = Os[q * 72 + u];
    }
}

// ============================================================
// K4: out = imgs + scale * (w_out @ attn_out), fp16 mma.
// A = w_out fp32->fp16 staged [64 c][72] (64 units + 8 pad — R13 bug was
// stride 40 here: rows overlapped, A operand scrambled).
// B = g_ao2 fp16 whole-K via cp.async [256 n][72].
// CTA 64c x 256n, 8 warps 2m x 4n, K=128 = 8 k16-steps.
// ============================================================
#define OA 0
#define OB 4608                       // 64*72
#define OUT_SMEM_BYTES ((4608 + 256 * 72) * 4)   // 92160

__global__ void __launch_bounds__(256) k_out_mma(const float* __restrict__ imgs,
                                                 const float* __restrict__ wout,
                                                 const float* __restrict__ scale_p,
                                                 float* __restrict__ out) {
    uint32_t* sA = dynsm + OA;    // [64 c][72]  half2, slot-permuted d-units
    uint32_t* sB = dynsm + OB;    // [256 n][72] half2, slot-permuted d-units
    const int b  = blockIdx.z;
    const int c0 = blockIdx.y * 64;
    const int n0 = blockIdx.x * 256;
    const int tid = threadIdx.x, lane = tid & 31, wid = tid >> 5;
    const int lr = lane >> 2, lc = lane & 3;
    const int wm = (wid >> 2) * 32;
    const int wn = (wid & 3) * 64;

    // B via cp.async (issue first for overlap)
#pragma unroll
    for (int it = 0; it < 16; it++) {
        int u = tid + it * 256;
        int n = u >> 4, c = u & 15;
        cp16(&sB[n * 72 + c * 4],
             g_ao2 + ((size_t)b * HWSZ + n0 + n) * 64 + c * 4);
    }
    CP_COMMIT();
    // A: load fp32 pairs, cvt fp16, store slot-permuted
    for (int e = tid; e < 64 * 64; e += 256) {
        int c = e >> 6, u = e & 63;
        int g = u >> 3, p = u & 7;
        int slot = (p < 4) ? 2 * p : 2 * (p - 4) + 1;
        float2 w2 = *(const float2*)&wout[(size_t)(c0 + c) * DV + 2 * u];
        sA[c * 72 + g * 8 + slot] = pack_h2(w2.x, w2.y);
    }
    CP_WAIT0();
    __syncthreads();

    float acc[2][8][4];
#pragma unroll
    for (int mf = 0; mf < 2; mf++)
#pragma unroll
        for (int nf = 0; nf < 8; nf++)
#pragma unroll
            for (int j = 0; j < 4; j++) acc[mf][nf][j] = 0.0f;

#pragma unroll
    for (int ks = 0; ks < 8; ks++) {
        uint2 aL[2], aH[2];
#pragma unroll
        for (int mf = 0; mf < 2; mf++) {
            int row = wm + mf * 16 + lr;
            aL[mf] = *(const uint2*)&sA[row * 72 + ks * 8 + 2 * lc];
            aH[mf] = *(const uint2*)&sA[(row + 8) * 72 + ks * 8 + 2 * lc];
        }
#pragma unroll
        for (int nf = 0; nf < 8; nf++) {
            uint2 bb = *(const uint2*)&sB[(wn + nf * 8 + lr) * 72 + ks * 8 + 2 * lc];
            mma_f16(acc[0][nf], aL[0].x, aH[0].x, aL[0].y, aH[0].y, bb.x, bb.y);
            mma_f16(acc[1][nf], aL[1].x, aH[1].x, aL[1].y, aH[1].y, bb.x, bb.y);
        }
    }

    const float s = *scale_p;
#pragma unroll
    for (int mf = 0; mf < 2; mf++)
#pragma unroll
        for (int nf = 0; nf < 8; nf++) {
            int row = c0 + wm + mf * 16 + lr;
            int col = wn + nf * 8 + 2 * lc;
            size_t i0 = ((size_t)b * CC + row) * HWSZ + n0 + col;
            size_t i1 = ((size_t)b * CC + row + 8) * HWSZ + n0 + col;
            float2 m0 = *(const float2*)&imgs[i0];
            float2 m1 = *(const float2*)&imgs[i1];
            *(float2*)&out[i0] = make_float2(m0.x + s * acc[mf][nf][0],
                                             m0.y + s * acc[mf][nf][1]);
            *(float2*)&out[i1] = make_float2(m1.x + s * acc[mf][nf][2],
                                             m1.y + s * acc[mf][nf][3]);
        }
}

// ============================================================
extern "C" void kernel_launch(void* const* d_in, const int* in_sizes, int n_in,
                              void* d_out, int out_size) {
    const float* imgs  = (const float*)d_in[0];
    const float* wqkv  = (const float*)d_in[1];
    const float* wout  = (const float*)d_in[2];
    const float* scale = (const float*)d_in[3];
    float* out = (float*)d_out;

    cudaFuncSetAttribute(k_qkv_mma,  cudaFuncAttributeMaxDynamicSharedMemorySize, GEMM_SMEM_BYTES);
    cudaFuncSetAttribute(k_attn_mma, cudaFuncAttributeMaxDynamicSharedMemorySize, SATT_SMEM_BYTES);
    cudaFuncSetAttribute(k_out_mma,  cudaFuncAttributeMaxDynamicSharedMemorySize, OUT_SMEM_BYTES);

    k_qkv_mma<<<dim3(16, 3, 16), 256, GEMM_SMEM_BYTES>>>(imgs, wqkv);

    k_attn_mma<<<dim3(32, 16), 256, SATT_SMEM_BYTES>>>();

    k_out_mma<<<dim3(16, 4, 16), 256, OUT_SMEM_BYTES>>>(imgs, wout, scale, out);
}